// round 4
// baseline (speedup 1.0000x reference)
#include <cuda_runtime.h>
#include <math.h>

// RoIPooling: feat [B,C,50,50] f32, rois [N,5] f32, img scalars -> out [N,C,7,7] f32.
// Bench: B=2, C=256, N=128, IMG=800.
//
// Two kernels:
//  1) transpose_in: feat[b][c][p] -> featT[b][p][c] with 128-bit ld/st (64x64 tiles)
//  2) roipool_main: block per (roi,oh), thread=channel; 7 register accumulators;
//     coalesced loads from featT; smem-staged direct writes to out (no outT).

#define C_DIM 256
#define FH 50
#define FW 50
#define NPIX (FH * FW)
#define OH 7
#define OW 7
#define MAX_B 4

__device__ float g_featT[MAX_B * NPIX * C_DIM];   // [b][p][c]

__device__ __forceinline__ float decode_dim(const void* p) {
    int v = *reinterpret_cast<const int*>(p);
    if (v > 0 && v < 1000000) return (float)v;   // int scalar (800 = 0x320)
    return __int_as_float(v);                     // float bits
}

// ---- feat [b][c][p] -> featT [b][p][c], 64x64 tiles, float4 both sides ----
__global__ void transpose_in(const float* __restrict__ feat) {
    __shared__ float t[64][65];   // [c_local][p_local], stride 65 (odd -> low conflicts)
    int b   = blockIdx.z;
    int tp0 = blockIdx.x * 64;    // pixel tile base
    int tc0 = blockIdx.y * 64;    // channel tile base
    int tx = threadIdx.x;         // 0..15
    int ty = threadIdx.y;         // 0..15

    // load: float4 along p
    #pragma unroll
    for (int j = 0; j < 4; ++j) {
        int cl = ty + 16 * j;
        int p0 = tp0 + 4 * tx;
        if (p0 + 3 < NPIX) {
            float4 v = *reinterpret_cast<const float4*>(
                feat + ((size_t)(b * C_DIM + tc0 + cl)) * NPIX + p0);
            t[cl][4 * tx + 0] = v.x;
            t[cl][4 * tx + 1] = v.y;
            t[cl][4 * tx + 2] = v.z;
            t[cl][4 * tx + 3] = v.w;
        } else {
            #pragma unroll
            for (int k = 0; k < 4; ++k)
                if (p0 + k < NPIX)
                    t[cl][4 * tx + k] =
                        feat[((size_t)(b * C_DIM + tc0 + cl)) * NPIX + p0 + k];
        }
    }
    __syncthreads();

    // store: float4 along c
    #pragma unroll
    for (int j = 0; j < 4; ++j) {
        int pl = ty + 16 * j;
        int p = tp0 + pl;
        if (p < NPIX) {
            float4 v;
            v.x = t[4 * tx + 0][pl];
            v.y = t[4 * tx + 1][pl];
            v.z = t[4 * tx + 2][pl];
            v.w = t[4 * tx + 3][pl];
            *reinterpret_cast<float4*>(
                g_featT + ((size_t)b * NPIX + p) * C_DIM + tc0 + 4 * tx) = v;
        }
    }
}

// ---- block per (roi, oh); thread = channel ----
__global__ void roipool_main(const float* __restrict__ rois,
                             const void* __restrict__ img_h_p,
                             const void* __restrict__ img_w_p,
                             float* __restrict__ out) {
    int oh = blockIdx.x % OH;
    int n  = blockIdx.x / OH;
    int c  = threadIdx.x;

    // uniform per-block bound computation (identical in every thread, no divergence)
    float img_h = decode_dim(img_h_p);
    float img_w = decode_dim(img_w_p);
    float sh = __fdiv_rn((float)FH, img_h);
    float sw = __fdiv_rn((float)FW, img_w);

    const float* r = rois + n * 5;
    int bidx = (int)r[0];
    // exact reference rounding: single rn-multiply, floor, clamps
    int x1 = max((int)floorf(__fmul_rn(r[1], sw)), 0);
    int y1 = max((int)floorf(__fmul_rn(r[2], sh)), 0);
    int x2 = min((int)floorf(__fmul_rn(r[3], sw)), FW);
    int y2 = min((int)floorf(__fmul_rn(r[4], sh)), FH);

    float bh = __fdiv_rn((float)max(y2 - y1, 1), (float)OH);
    float bw = __fdiv_rn((float)max(x2 - x1, 1), (float)OW);
    float y1f = (float)y1, x1f = (float)x1;

    // mul then add, each rn (no FMA contraction) — matches jnp
    int ys = (int)floorf(__fadd_rn(y1f, __fmul_rn((float)oh,       bh)));
    int ye = (int)floorf(__fadd_rn(y1f, __fmul_rn((float)(oh + 1), bh)));
    ys = min(max(ys, 0), FH - 1);
    ye = min(max(ye, 0), FH);

    int xs[OW], xe[OW];
    #pragma unroll
    for (int ow = 0; ow < OW; ++ow) {
        int a = (int)floorf(__fadd_rn(x1f, __fmul_rn((float)ow,       bw)));
        int b = (int)floorf(__fadd_rn(x1f, __fmul_rn((float)(ow + 1), bw)));
        xs[ow] = min(max(a, 0), FW - 1);
        xe[ow] = min(max(b, 0), FW);
    }

    const float* base = g_featT + (size_t)bidx * NPIX * C_DIM + c;

    float acc[OW];
    #pragma unroll
    for (int ow = 0; ow < OW; ++ow) acc[ow] = -INFINITY;

    for (int y = ys; y < ye; ++y) {
        const float* rowp = base + (size_t)(y * FW) * C_DIM;
        #pragma unroll
        for (int ow = 0; ow < OW; ++ow) {
            for (int x = xs[ow]; x < xe[ow]; ++x) {
                acc[ow] = fmaxf(acc[ow], __ldg(rowp + x * C_DIM));
            }
        }
    }

    __shared__ float s[C_DIM * OW];
    bool yv = (ye > ys);
    #pragma unroll
    for (int ow = 0; ow < OW; ++ow) {
        bool valid = yv && (xe[ow] > xs[ow]);
        s[c * OW + ow] = valid ? acc[ow] : 0.0f;   // stride-7 banks: conflict-free
    }
    __syncthreads();

    // flat coalesced-ish drain: j = cw*7 + ow
    size_t outbase = (size_t)n * (C_DIM * OH * OW) + oh * OW;
    #pragma unroll
    for (int k = 0; k < OW; ++k) {
        int j = c + k * C_DIM;       // 0..1791
        int cw = j / OW;
        int ow = j % OW;
        out[outbase + (size_t)cw * (OH * OW) + ow] = s[j];
    }
}

extern "C" void kernel_launch(void* const* d_in, const int* in_sizes, int n_in,
                              void* d_out, int out_size) {
    const float* feat = (const float*)d_in[0];
    const float* rois = (const float*)d_in[1];
    const void*  imh  = d_in[2];
    const void*  imw  = d_in[3];
    float* out = (float*)d_out;

    int B = in_sizes[0] / (C_DIM * NPIX);
    int nrois = in_sizes[1] / 5;

    dim3 tb(16, 16);
    dim3 tg((NPIX + 63) / 64, C_DIM / 64, B);
    transpose_in<<<tg, tb>>>(feat);

    roipool_main<<<nrois * OH, C_DIM>>>(rois, imh, imw, out);
}

// round 5
// speedup vs baseline: 1.7458x; 1.7458x over previous
#include <cuda_runtime.h>
#include <math.h>

// RoIPooling: feat [B,C,50,50] f32, rois [N,5] f32, img scalars -> out [N,C,7,7] f32.
// Bench: B=2, C=256, N=128, IMG=800.
//
// 1) transpose_in : feat[b][c][p] -> featT[b][p][c], float4 both sides
// 2) roipool_main : block per bin, thread=channel; block-uniform offset table in
//                   smem -> flat loop of independent coalesced LDGs; writes outT[bin][c]
// 3) transpose_out: outT[n][q][c] -> out[n][c][q], smem-staged, coalesced both sides

#define C_DIM 256
#define FH 50
#define FW 50
#define NPIX (FH * FW)
#define OH 7
#define OW 7
#define QD (OH * OW)
#define MAX_B 4
#define MAX_ROIS 512
#define MAX_CNT 96   // bin span <= 8x8 = 64; headroom

__device__ float g_featT[MAX_B * NPIX * C_DIM];        // [b][p][c]
__device__ float g_outT[MAX_ROIS * QD * C_DIM];        // [n][q][c]

__device__ __forceinline__ float decode_dim(const void* p) {
    int v = *reinterpret_cast<const int*>(p);
    if (v > 0 && v < 1000000) return (float)v;   // int scalar (800 = 0x320)
    return __int_as_float(v);                     // float bits
}

// ---- feat [b][c][p] -> featT [b][p][c], 64x64 tiles, float4 both sides ----
__global__ void transpose_in(const float* __restrict__ feat) {
    __shared__ float t[64][65];
    int b   = blockIdx.z;
    int tp0 = blockIdx.x * 64;
    int tc0 = blockIdx.y * 64;
    int tx = threadIdx.x;   // 0..15
    int ty = threadIdx.y;   // 0..15

    #pragma unroll
    for (int j = 0; j < 4; ++j) {
        int cl = ty + 16 * j;
        int p0 = tp0 + 4 * tx;
        if (p0 + 3 < NPIX) {
            float4 v = *reinterpret_cast<const float4*>(
                feat + ((size_t)(b * C_DIM + tc0 + cl)) * NPIX + p0);
            t[cl][4 * tx + 0] = v.x;
            t[cl][4 * tx + 1] = v.y;
            t[cl][4 * tx + 2] = v.z;
            t[cl][4 * tx + 3] = v.w;
        } else {
            #pragma unroll
            for (int k = 0; k < 4; ++k)
                if (p0 + k < NPIX)
                    t[cl][4 * tx + k] =
                        feat[((size_t)(b * C_DIM + tc0 + cl)) * NPIX + p0 + k];
        }
    }
    __syncthreads();

    #pragma unroll
    for (int j = 0; j < 4; ++j) {
        int pl = ty + 16 * j;
        int p = tp0 + pl;
        if (p < NPIX) {
            float4 v;
            v.x = t[4 * tx + 0][pl];
            v.y = t[4 * tx + 1][pl];
            v.z = t[4 * tx + 2][pl];
            v.w = t[4 * tx + 3][pl];
            *reinterpret_cast<float4*>(
                g_featT + ((size_t)b * NPIX + p) * C_DIM + tc0 + 4 * tx) = v;
        }
    }
}

// ---- block per bin; thread = channel; flat offset-table loop ----
__global__ void roipool_main(const float* __restrict__ rois,
                             const void* __restrict__ img_h_p,
                             const void* __restrict__ img_w_p) {
    int bin = blockIdx.x;
    int c   = threadIdx.x;
    int ow = bin % OW;
    int oh = (bin / OW) % OH;
    int n  = bin / QD;

    __shared__ int s_offs[MAX_CNT];   // element offsets into featT plane, pre-multiplied by C_DIM
    __shared__ int s_count;
    __shared__ int s_base;

    // block-uniform bound math (every thread computes the same values; no divergence)
    float img_h = decode_dim(img_h_p);
    float img_w = decode_dim(img_w_p);
    float sh = __fdiv_rn((float)FH, img_h);
    float sw = __fdiv_rn((float)FW, img_w);

    const float* r = rois + n * 5;
    int bidx = (int)r[0];
    int x1 = max((int)floorf(__fmul_rn(r[1], sw)), 0);
    int y1 = max((int)floorf(__fmul_rn(r[2], sh)), 0);
    int x2 = min((int)floorf(__fmul_rn(r[3], sw)), FW);
    int y2 = min((int)floorf(__fmul_rn(r[4], sh)), FH);

    float bh = __fdiv_rn((float)max(y2 - y1, 1), (float)OH);
    float bw = __fdiv_rn((float)max(x2 - x1, 1), (float)OW);
    float y1f = (float)y1, x1f = (float)x1;
    // mul then add, each correctly rounded (no FMA contraction) — matches jnp
    int ys = (int)floorf(__fadd_rn(y1f, __fmul_rn((float)oh,       bh)));
    int ye = (int)floorf(__fadd_rn(y1f, __fmul_rn((float)(oh + 1), bh)));
    int xs = (int)floorf(__fadd_rn(x1f, __fmul_rn((float)ow,       bw)));
    int xe = (int)floorf(__fadd_rn(x1f, __fmul_rn((float)(ow + 1), bw)));
    ys = min(max(ys, 0), FH - 1);
    ye = min(max(ye, 0), FH);
    xs = min(max(xs, 0), FW - 1);
    xe = min(max(xe, 0), FW);

    int rows = ye - ys;
    int cols = xe - xs;
    bool valid = (rows > 0) && (cols > 0);
    int count = valid ? rows * cols : 0;

    if (c == 0) {
        s_count = count;
        s_base  = bidx * (NPIX * C_DIM);
    }
    if (c < count) {
        int yy = ys + c / cols;
        int xx = xs + c % cols;
        s_offs[c] = (yy * FW + xx) * C_DIM;
    }
    __syncthreads();

    int cnt = s_count;
    const float* base = g_featT + s_base + c;

    float m = -INFINITY;
    int i = 0;
    // 4-way unrolled flat loop: all loads independent -> high MLP
    for (; i + 4 <= cnt; i += 4) {
        float a0 = __ldg(base + s_offs[i + 0]);
        float a1 = __ldg(base + s_offs[i + 1]);
        float a2 = __ldg(base + s_offs[i + 2]);
        float a3 = __ldg(base + s_offs[i + 3]);
        m = fmaxf(m, fmaxf(fmaxf(a0, a1), fmaxf(a2, a3)));
    }
    for (; i < cnt; ++i) {
        m = fmaxf(m, __ldg(base + s_offs[i]));
    }

    g_outT[(size_t)bin * C_DIM + c] = (cnt > 0) ? m : 0.0f;
}

// ---- outT [n][q][c] -> out [n][c][q]; block per (n, channel-half) ----
__global__ void transpose_out(float* __restrict__ out) {
    __shared__ float s[128 * QD];   // [c_local][q], stride 49 (odd -> conflict-free)
    int n = blockIdx.x;
    int h = blockIdx.y;             // channel half: 0 or 1
    int tid = threadIdx.x;          // 0..255

    const float* src = g_outT + (size_t)n * (QD * C_DIM) + h * 128;
    for (int idx = tid; idx < QD * 128; idx += 256) {
        int q = idx >> 7;           // idx / 128
        int cl = idx & 127;         // idx % 128
        s[cl * QD + q] = src[(size_t)q * C_DIM + cl];   // gmem coalesced, smem stride-49
    }
    __syncthreads();

    float* dst = out + (size_t)n * (C_DIM * QD) + (size_t)h * 128 * QD;
    for (int idx = tid; idx < 128 * QD; idx += 256) {
        dst[idx] = s[idx];          // both sides linear/coalesced
    }
}

extern "C" void kernel_launch(void* const* d_in, const int* in_sizes, int n_in,
                              void* d_out, int out_size) {
    const float* feat = (const float*)d_in[0];
    const float* rois = (const float*)d_in[1];
    const void*  imh  = d_in[2];
    const void*  imw  = d_in[3];
    float* out = (float*)d_out;

    int B = in_sizes[0] / (C_DIM * NPIX);
    int nrois = in_sizes[1] / 5;
    int nbins = nrois * QD;

    dim3 tb(16, 16);
    dim3 tg((NPIX + 63) / 64, C_DIM / 64, B);
    transpose_in<<<tg, tb>>>(feat);

    roipool_main<<<nbins, C_DIM>>>(rois, imh, imw);

    dim3 og(nrois, 2);
    transpose_out<<<og, 256>>>(out);
}

// round 6
// speedup vs baseline: 2.2821x; 1.3072x over previous
#include <cuda_runtime.h>
#include <math.h>

// RoIPooling: feat [B,C,50,50] f32, rois [N,5] f32, img scalars -> out [N,C,7,7] f32.
// Bench: B=2, C=256, N=128, IMG=800.
//
// 3-stage pipeline, each stage sized for latency hiding:
//  1) transpose_in : feat[b][c][p] -> featT[b][p][c]; 32x32 tiles, 1264 blocks,
//                    one LDG.128 + one STG.128 per thread.
//  2) roipool_main : block per bin (6272 blocks, 64 threads); thread = 4 channels
//                    (float4); block-uniform smem offset table -> flat unrolled
//                    loop of independent coalesced 16B loads.
//  3) transpose_out: g_outT[n][q][c] -> out[n][c][q]; coalesced reads, float4 drain.

#define C_DIM 256
#define FH 50
#define FW 50
#define NPIX (FH * FW)
#define OH 7
#define OW 7
#define QD (OH * OW)
#define MAX_B 4
#define MAX_ROIS 512
#define MAX_CNT 96   // bin span <= 8x8 = 64

__device__ float g_featT[MAX_B * NPIX * C_DIM];   // [b][p][c]
__device__ float g_outT[MAX_ROIS * QD * C_DIM];   // [n][q][c]

__device__ __forceinline__ float decode_dim(const void* p) {
    int v = *reinterpret_cast<const int*>(p);
    if (v > 0 && v < 1000000) return (float)v;   // int scalar (800 = 0x320)
    return __int_as_float(v);                     // float bits
}

// ---- feat [b][c][p] -> featT [b][p][c]; 32x32 tiles, float4 both sides ----
__global__ void transpose_in(const float* __restrict__ feat) {
    __shared__ float s[32][33];      // [c_local][p_local], padded
    int b   = blockIdx.z;
    int tp0 = blockIdx.x * 32;       // pixel tile base
    int tc0 = blockIdx.y * 32;       // channel tile base
    int tid = threadIdx.x;           // 0..255

    // load: thread -> (c_local = tid/8, p4 = tid%8); 8 float4 = 128B per channel row
    {
        int cl = tid >> 3;
        int p0 = tp0 + ((tid & 7) << 2);
        if (p0 < NPIX) {             // NPIX%4==0 and p0%4==0 -> p0+3 < NPIX too
            float4 v = *reinterpret_cast<const float4*>(
                feat + ((size_t)(b * C_DIM + tc0 + cl)) * NPIX + p0);
            int pl = (tid & 7) << 2;
            s[cl][pl + 0] = v.x;
            s[cl][pl + 1] = v.y;
            s[cl][pl + 2] = v.z;
            s[cl][pl + 3] = v.w;
        }
    }
    __syncthreads();

    // store: thread -> (p_local = tid/8, c4 = tid%8); 8 float4 = 128B per pixel row
    {
        int pl = tid >> 3;
        int p  = tp0 + pl;
        if (p < NPIX) {
            int c0 = (tid & 7) << 2;
            float4 v;
            v.x = s[c0 + 0][pl];
            v.y = s[c0 + 1][pl];
            v.z = s[c0 + 2][pl];
            v.w = s[c0 + 3][pl];
            *reinterpret_cast<float4*>(
                g_featT + ((size_t)b * NPIX + p) * C_DIM + tc0 + c0) = v;
        }
    }
}

__device__ __forceinline__ float4 f4max(float4 a, float4 b) {
    return make_float4(fmaxf(a.x, b.x), fmaxf(a.y, b.y),
                       fmaxf(a.z, b.z), fmaxf(a.w, b.w));
}

// ---- block per bin; 64 threads; thread = 4 channels (float4) ----
__global__ void __launch_bounds__(64) roipool_main(const float* __restrict__ rois,
                             const void* __restrict__ img_h_p,
                             const void* __restrict__ img_w_p) {
    int bin = blockIdx.x;
    int t   = threadIdx.x;           // 0..63
    int ow = bin % OW;
    int oh = (bin / OW) % OH;
    int n  = bin / QD;

    __shared__ int s_offs[MAX_CNT];  // featT element offsets, pre-multiplied by C_DIM

    // block-uniform bound math (identical in all threads)
    float img_h = decode_dim(img_h_p);
    float img_w = decode_dim(img_w_p);
    float sh = __fdiv_rn((float)FH, img_h);
    float sw = __fdiv_rn((float)FW, img_w);

    const float* r = rois + n * 5;
    int bidx = (int)r[0];
    int x1 = max((int)floorf(__fmul_rn(r[1], sw)), 0);
    int y1 = max((int)floorf(__fmul_rn(r[2], sh)), 0);
    int x2 = min((int)floorf(__fmul_rn(r[3], sw)), FW);
    int y2 = min((int)floorf(__fmul_rn(r[4], sh)), FH);

    float bh = __fdiv_rn((float)max(y2 - y1, 1), (float)OH);
    float bw = __fdiv_rn((float)max(x2 - x1, 1), (float)OW);
    float y1f = (float)y1, x1f = (float)x1;
    // mul then add, each correctly rounded (no FMA contraction) — matches jnp
    int ys = (int)floorf(__fadd_rn(y1f, __fmul_rn((float)oh,       bh)));
    int ye = (int)floorf(__fadd_rn(y1f, __fmul_rn((float)(oh + 1), bh)));
    int xs = (int)floorf(__fadd_rn(x1f, __fmul_rn((float)ow,       bw)));
    int xe = (int)floorf(__fadd_rn(x1f, __fmul_rn((float)(ow + 1), bw)));
    ys = min(max(ys, 0), FH - 1);
    ye = min(max(ye, 0), FH);
    xs = min(max(xs, 0), FW - 1);
    xe = min(max(xe, 0), FW);

    int rows = ye - ys;
    int cols = xe - xs;
    int count = (rows > 0 && cols > 0) ? rows * cols : 0;

    if (t < count) {
        int yy = ys + t / cols;
        int xx = xs + t % cols;
        s_offs[t] = (yy * FW + xx) * C_DIM;
    }
    __syncthreads();

    const float* base = g_featT + (size_t)bidx * (NPIX * C_DIM) + (t << 2);

    float4 m = make_float4(-INFINITY, -INFINITY, -INFINITY, -INFINITY);
    int i = 0;
    for (; i + 4 <= count; i += 4) {
        float4 a0 = *reinterpret_cast<const float4*>(base + s_offs[i + 0]);
        float4 a1 = *reinterpret_cast<const float4*>(base + s_offs[i + 1]);
        float4 a2 = *reinterpret_cast<const float4*>(base + s_offs[i + 2]);
        float4 a3 = *reinterpret_cast<const float4*>(base + s_offs[i + 3]);
        m = f4max(m, f4max(f4max(a0, a1), f4max(a2, a3)));
    }
    for (; i < count; ++i) {
        m = f4max(m, *reinterpret_cast<const float4*>(base + s_offs[i]));
    }
    if (count == 0) m = make_float4(0.f, 0.f, 0.f, 0.f);

    *reinterpret_cast<float4*>(g_outT + (size_t)bin * C_DIM + (t << 2)) = m;
}

// ---- g_outT [n][q][c] -> out [n][c][q]; block per (n, channel-half) ----
__global__ void transpose_out(float* __restrict__ out) {
    __shared__ float s[128 * QD];    // [c_local][q], stride 49 (odd -> conflict-free)
    int n = blockIdx.x;
    int h = blockIdx.y;              // channel half
    int tid = threadIdx.x;           // 0..255

    const float* src = g_outT + (size_t)n * (QD * C_DIM) + h * 128;
    for (int idx = tid; idx < QD * 128; idx += 256) {
        int q  = idx >> 7;
        int cl = idx & 127;
        s[cl * QD + q] = src[(size_t)q * C_DIM + cl];   // gmem coalesced
    }
    __syncthreads();

    // linear float4 drain: 128*49 = 6272 floats = 1568 float4
    float4* dst = reinterpret_cast<float4*>(
        out + (size_t)n * (C_DIM * QD) + (size_t)h * 128 * QD);
    const float4* ss = reinterpret_cast<const float4*>(s);
    for (int idx = tid; idx < (128 * QD) / 4; idx += 256) {
        dst[idx] = ss[idx];
    }
}

extern "C" void kernel_launch(void* const* d_in, const int* in_sizes, int n_in,
                              void* d_out, int out_size) {
    const float* feat = (const float*)d_in[0];
    const float* rois = (const float*)d_in[1];
    const void*  imh  = d_in[2];
    const void*  imw  = d_in[3];
    float* out = (float*)d_out;

    int B = in_sizes[0] / (C_DIM * NPIX);
    int nrois = in_sizes[1] / 5;
    int nbins = nrois * QD;

    dim3 tg((NPIX + 31) / 32, C_DIM / 32, B);
    transpose_in<<<tg, 256>>>(feat);

    roipool_main<<<nbins, 64>>>(rois, imh, imw);

    dim3 og(nrois, 2);
    transpose_out<<<og, 256>>>(out);
}